// round 4
// baseline (speedup 1.0000x reference)
#include <cuda_runtime.h>

// Problem constants
#define S     8192
#define BATCH 8
#define IN1   229
#define MC    48     // model channels (out_f of q/k/v)
#define OUTF  88     // onset/frame output features
#define IN2   136    // MC + OUTF
#define NC    144    // 3*MC fused qkv columns
#define KW    31     // window
#define HALF  15
#define TT    128    // token tile per attention block
#define NROW  (BATCH*S)   // 65536

// ---------------- scratch (static device allocations are allowed) ----------------
__device__ float g_qkv[NROW * NC];   // fused q|k|v projections (reused by both stages)
__device__ float g_y[NROW * IN2];    // concat(onset, x_ln) input of stage 2
__device__ float g_B[232 * NC];      // transposed weight matrix [Kpad][144]

// ---------------- weight transpose/stage: B[k][o] = W_sel[o%48][k] ----------------
__global__ void prep_B(const float* __restrict__ Wq, const float* __restrict__ Wk,
                       const float* __restrict__ Wv, int KD, int KP) {
    int idx = blockIdx.x * 256 + threadIdx.x;
    if (idx >= KP * NC) return;
    int k = idx / NC, o = idx % NC;
    const float* W = (o < MC) ? Wq : (o < 2 * MC) ? Wk : Wv;
    int row = o - (o < MC ? 0 : (o < 2 * MC ? MC : 2 * MC));
    g_B[idx] = (k < KD) ? W[row * KD + k] : 0.f;
}

// ---------------- fp32 GEMM with packed f32x2 FFMA ----------------
// C[M,144] = A[M,KD] * B[KD,144].  BM=128, BN=144, 256 thr, 8(M)x9(N) per thread.
#define BM 128
template <bool FROM_Y>
__global__ __launch_bounds__(256, 2)
void gemm_k(const float* __restrict__ Aext, int lda, int KD, int KP) {
    __shared__ float sA[2][8][132];
    __shared__ float sB[2][8][NC];
    const float* A = FROM_Y ? g_y : Aext;

    int tid = threadIdx.x;
    int ty = tid >> 4;        // 0..15 -> rows ty*8..ty*8+7
    int tx = tid & 15;        // 0..15 -> cols tx*9..tx*9+8
    int rowBase = blockIdx.x * BM;

    unsigned long long acc[9][4];
#pragma unroll
    for (int n = 0; n < 9; n++)
#pragma unroll
        for (int m = 0; m < 4; m++) acc[n][m] = 0ull;

    int nchunk = KP >> 3;

    // prologue: load chunk 0
    {
#pragma unroll
        for (int p = 0; p < 4; p++) {
            int idx = tid + p * 256;
            int kk = idx & 7, r = idx >> 3;
            sA[0][kk][r] = (kk < KD) ? A[(rowBase + r) * lda + kk] : 0.f;
        }
        for (int idx = tid; idx < 8 * NC; idx += 256) {
            int kk = idx / NC, o = idx - kk * NC;
            sB[0][kk][o] = g_B[kk * NC + o];
        }
    }
    __syncthreads();

    for (int c = 0; c < nchunk; c++) {
        int cur = c & 1, nxt = cur ^ 1;
        if (c + 1 < nchunk) {
            int k0 = (c + 1) * 8;
#pragma unroll
            for (int p = 0; p < 4; p++) {
                int idx = tid + p * 256;
                int kk = idx & 7, r = idx >> 3;
                int k = k0 + kk;
                sA[nxt][kk][r] = (k < KD) ? A[(rowBase + r) * lda + k] : 0.f;
            }
            for (int idx = tid; idx < 8 * NC; idx += 256) {
                int kk = idx / NC, o = idx - kk * NC;
                sB[nxt][kk][o] = g_B[(k0 + kk) * NC + o];
            }
        }
#pragma unroll
        for (int kk = 0; kk < 8; kk++) {
            float4 a0 = *(const float4*)&sA[cur][kk][ty * 8];
            float4 a1 = *(const float4*)&sA[cur][kk][ty * 8 + 4];
            unsigned long long av[4];
            asm("mov.b64 %0,{%1,%2};" : "=l"(av[0]) : "f"(a0.x), "f"(a0.y));
            asm("mov.b64 %0,{%1,%2};" : "=l"(av[1]) : "f"(a0.z), "f"(a0.w));
            asm("mov.b64 %0,{%1,%2};" : "=l"(av[2]) : "f"(a1.x), "f"(a1.y));
            asm("mov.b64 %0,{%1,%2};" : "=l"(av[3]) : "f"(a1.z), "f"(a1.w));
#pragma unroll
            for (int n = 0; n < 9; n++) {
                float bv = sB[cur][kk][tx * 9 + n];
                unsigned long long bd;
                asm("mov.b64 %0,{%1,%1};" : "=l"(bd) : "f"(bv));
#pragma unroll
                for (int m = 0; m < 4; m++)
                    asm("fma.rn.f32x2 %0, %1, %2, %0;"
                        : "+l"(acc[n][m]) : "l"(av[m]), "l"(bd));
            }
        }
        __syncthreads();
    }

    // epilogue
#pragma unroll
    for (int n = 0; n < 9; n++) {
        int col = tx * 9 + n;
#pragma unroll
        for (int m = 0; m < 4; m++) {
            float lo, hi;
            asm("mov.b64 {%0,%1},%2;" : "=f"(lo), "=f"(hi) : "l"(acc[n][m]));
            g_qkv[(rowBase + ty * 8 + 2 * m) * NC + col] = lo;
            g_qkv[(rowBase + ty * 8 + 2 * m + 1) * NC + col] = hi;
        }
    }
}

// ---------------- fused attention + LN + sigmoid-linear ----------------
struct AttSmem {
    float k[TT + 2 * HALF][49];   // padded stride vs bank conflicts
    float v[TT + 2 * HALF][49];
    float qx[TT][MC];             // q, then overwritten with x / x_ln (stride 48 for vec4)
    float rel[MC][32];
    float w[OUTF][MC];            // linear weight (stride 48 -> float4)
    float gamma[MC];
    float beta[MC];
    float bias[OUTF];
};

template <bool FIRST>
__global__ __launch_bounds__(256)
void att_kernel(const float* __restrict__ rel,
                const float* __restrict__ lng, const float* __restrict__ lnb,
                const float* __restrict__ Wlin, const float* __restrict__ blin,
                float* __restrict__ out_lin,    // sigmoid(linear) [NROW,88]
                float* __restrict__ out_a)      // attn weights [NROW,8,31] (stage1 only)
{
    extern __shared__ char smraw[];
    AttSmem& sm = *reinterpret_cast<AttSmem*>(smraw);
    int tid = threadIdx.x;
    int t0 = blockIdx.x * TT;
    int b  = blockIdx.y;

    // ---- load K/V window, Q tile, rel, weights ----
    for (int idx = tid; idx < (TT + 2 * HALF) * MC; idx += 256) {
        int r = idx / MC, c = idx - r * MC;
        int t = t0 - HALF + r;
        float kv = 0.f, vv = 0.f;
        if (t >= 0 && t < S) {
            int g = (b * S + t) * NC;
            kv = g_qkv[g + MC + c];
            vv = g_qkv[g + 2 * MC + c];
        }
        sm.k[r][c] = kv;
        sm.v[r][c] = vv;
    }
    for (int idx = tid; idx < TT * MC; idx += 256) {
        int r = idx / MC, c = idx - r * MC;
        sm.qx[r][c] = g_qkv[(b * S + t0 + r) * NC + c];
    }
    for (int idx = tid; idx < MC * KW; idx += 256) {
        int c = idx / KW, j = idx - c * KW;
        sm.rel[c][j] = rel[idx];
    }
    for (int idx = tid; idx < OUTF * MC; idx += 256)
        sm.w[idx / MC][idx % MC] = Wlin[idx];
    if (tid < MC) { sm.gamma[tid] = lng[tid]; sm.beta[tid] = lnb[tid]; }
    if (tid < OUTF) sm.bias[tid] = blin[tid];
    __syncthreads();

    // ---- windowed attention: one (token, group) item per thread step ----
    for (int i = 0; i < (TT * 8) / 256; i++) {
        int item = i * 256 + tid;
        int tl = item >> 3, g = item & 7;
        int c0 = g * 6;
        float qv[6];
#pragma unroll
        for (int c = 0; c < 6; c++) qv[c] = sm.qx[tl][c0 + c];

        float e[KW];
        float mx = -1e30f;
#pragma unroll
        for (int j = 0; j < KW; j++) {
            float s = 0.f;
#pragma unroll
            for (int c = 0; c < 6; c++)
                s = fmaf(qv[c], sm.k[tl + j][c0 + c] + sm.rel[c0 + c][j], s);
            e[j] = s;
            mx = fmaxf(mx, s);
        }
        float sum = 0.f;
#pragma unroll
        for (int j = 0; j < KW; j++) { e[j] = __expf(e[j] - mx); sum += e[j]; }
        float inv = 1.f / sum;

        if (FIRST) {
            int ab = ((b * S + t0 + tl) * 8 + g) * KW;
#pragma unroll
            for (int j = 0; j < KW; j++) out_a[ab + j] = e[j] * inv;
        }

        float xo[6];
#pragma unroll
        for (int c = 0; c < 6; c++) {
            float s = 0.f;
#pragma unroll
            for (int j = 0; j < KW; j++) s = fmaf(e[j], sm.v[tl + j][c0 + c], s);
            xo[c] = s * inv;
        }
        // only this thread ever touches slice (tl, g): safe to overwrite q with x
#pragma unroll
        for (int c = 0; c < 6; c++) sm.qx[tl][c0 + c] = xo[c];
    }
    __syncthreads();

    // ---- LayerNorm over 48 channels; write normalized x (and y tail for stage1) ----
    if (tid < TT) {
        float s = 0.f;
        for (int c = 0; c < MC; c++) s += sm.qx[tid][c];
        float mu = s * (1.f / MC);
        float v2 = 0.f;
        for (int c = 0; c < MC; c++) { float d = sm.qx[tid][c] - mu; v2 = fmaf(d, d, v2); }
        float rstd = rsqrtf(v2 * (1.f / MC) + 1e-5f);
        int grow = b * S + t0 + tid;
        for (int c = 0; c < MC; c++) {
            float xn = (sm.qx[tid][c] - mu) * rstd * sm.gamma[c] + sm.beta[c];
            sm.qx[tid][c] = xn;
            if (FIRST) g_y[grow * IN2 + OUTF + c] = xn;
        }
    }
    __syncthreads();

    // ---- sigmoid(x_ln @ W^T + b): 128x88 outputs ----
    for (int i = 0; i < (TT * OUTF) / 256; i++) {
        int item = i * 256 + tid;
        int tl = item / OUTF, o = item - tl * OUTF;
        const float4* xr = (const float4*)sm.qx[tl];
        const float4* wr = (const float4*)sm.w[o];
        float acc = sm.bias[o];
#pragma unroll
        for (int c = 0; c < MC / 4; c++) {
            float4 xv = xr[c], wv = wr[c];
            acc = fmaf(xv.x, wv.x, acc); acc = fmaf(xv.y, wv.y, acc);
            acc = fmaf(xv.z, wv.z, acc); acc = fmaf(xv.w, wv.w, acc);
        }
        float sg = 1.f / (1.f + __expf(-acc));
        int grow = b * S + t0 + tl;
        out_lin[grow * OUTF + o] = sg;
        if (FIRST) g_y[grow * IN2 + o] = sg;   // concat head
    }
}

// ---------------- launch ----------------
extern "C" void kernel_launch(void* const* d_in, const int* in_sizes, int n_in,
                              void* d_out, int out_size) {
    (void)in_sizes; (void)n_in; (void)out_size;
    const float* spec = (const float*)d_in[0];
    const float* Wq1  = (const float*)d_in[1];
    const float* Wk1  = (const float*)d_in[2];
    const float* Wv1  = (const float*)d_in[3];
    const float* rel1 = (const float*)d_in[4];
    const float* ln1g = (const float*)d_in[5];
    const float* ln1b = (const float*)d_in[6];
    const float* Wo   = (const float*)d_in[7];
    const float* bo   = (const float*)d_in[8];
    const float* Wq2  = (const float*)d_in[9];
    const float* Wk2  = (const float*)d_in[10];
    const float* Wv2  = (const float*)d_in[11];
    const float* rel2 = (const float*)d_in[12];
    const float* ln2g = (const float*)d_in[13];
    const float* ln2b = (const float*)d_in[14];
    const float* Wf   = (const float*)d_in[15];
    const float* bf   = (const float*)d_in[16];

    float* out = (float*)d_out;
    float* out_frame = out;                        // [NROW, 88]
    float* out_onset = out + (size_t)NROW * OUTF;  // [NROW, 88]
    float* out_a     = out + (size_t)2 * NROW * OUTF;  // [NROW, 8, 31]

    cudaFuncSetAttribute(att_kernel<true>,  cudaFuncAttributeMaxDynamicSharedMemorySize,
                         (int)sizeof(AttSmem));
    cudaFuncSetAttribute(att_kernel<false>, cudaFuncAttributeMaxDynamicSharedMemorySize,
                         (int)sizeof(AttSmem));

    dim3 attGrid(S / TT, BATCH);

    // stage 1
    prep_B<<<(232 * NC + 255) / 256, 256>>>(Wq1, Wk1, Wv1, IN1, 232);
    gemm_k<false><<<NROW / BM, 256>>>(spec, IN1, IN1, 232);
    att_kernel<true><<<attGrid, 256, sizeof(AttSmem)>>>(
        rel1, ln1g, ln1b, Wo, bo, out_onset, out_a);

    // stage 2
    prep_B<<<(IN2 * NC + 255) / 256, 256>>>(Wq2, Wk2, Wv2, IN2, IN2);
    gemm_k<true><<<NROW / BM, 256>>>(nullptr, IN2, IN2, IN2);
    att_kernel<false><<<attGrid, 256, sizeof(AttSmem)>>>(
        rel2, ln2g, ln2b, Wf, bf, out_frame, nullptr);
}

// round 6
// speedup vs baseline: 1.1380x; 1.1380x over previous
#include <cuda_runtime.h>

// Problem constants
#define S     8192
#define BATCH 8
#define IN1   229
#define MC    48     // model channels (out_f of q/k/v)
#define OUTF  88     // onset/frame output features
#define IN2   136    // MC + OUTF
#define NC    144    // 3*MC fused qkv columns
#define KW    31     // window
#define HALF  15
#define TT    64     // token tile per attention block
#define NROW  (BATCH*S)   // 65536

// ---------------- scratch ----------------
__device__ float g_qkv[NROW * NC];   // fused q|k|v projections (reused by both stages)
__device__ float g_y[NROW * IN2];    // concat(onset, x_ln) input of stage 2
__device__ float g_B[232 * NC];      // transposed weight matrix [Kpad][144]

// ---------------- weight transpose/stage: B[k][o] = W_sel[o%48][k] ----------------
__global__ void prep_B(const float* __restrict__ Wq, const float* __restrict__ Wk,
                       const float* __restrict__ Wv, int KD, int KP) {
    int idx = blockIdx.x * 256 + threadIdx.x;
    if (idx >= KP * NC) return;
    int k = idx / NC, o = idx % NC;
    const float* W = (o < MC) ? Wq : (o < 2 * MC) ? Wk : Wv;
    int row = o - (o < MC ? 0 : (o < 2 * MC ? MC : 2 * MC));
    g_B[idx] = (k < KD) ? W[row * KD + k] : 0.f;
}

// ---------------- fp32 GEMM, packed f32x2 FFMA, zero-MOV inner loop ----------------
// C[M,144] = A[M,KD] * B[KD,144].  BM=128, 256 thr.
// Thread map: tx = tid&7 -> 18 cols (9 col-pairs), ty = tid>>3 -> 4 rows.
// A duplicated in smem ({a,a} pairs) -> LDS.64; B natural col pairs -> LDS.64.
#define BM 128
template <bool FROM_Y>
__global__ __launch_bounds__(256, 2)
void gemm_k(const float* __restrict__ Aext, int lda, int KD, int KP) {
    __shared__ __align__(16) float sAd[2][8][264];  // duplicated pairs: [2r],[2r+1]
    __shared__ __align__(16) float sB[2][8][NC];
    const float* A = FROM_Y ? g_y : Aext;

    int tid = threadIdx.x;
    int tx = tid & 7;         // col group: cols tx*18 .. tx*18+17
    int ty = tid >> 3;        // row group: rows ty*4 .. ty*4+3
    int rowBase = blockIdx.x * BM;

    unsigned long long acc[9][4];
#pragma unroll
    for (int n = 0; n < 9; n++)
#pragma unroll
        for (int m = 0; m < 4; m++) acc[n][m] = 0ull;

    int nchunk = KP >> 3;

    // prologue: stage chunk 0
    {
#pragma unroll
        for (int p = 0; p < 4; p++) {
            int idx = tid + p * 256;
            int kk = idx & 7, r = idx >> 3;
            float v = (kk < KD) ? A[(rowBase + r) * lda + kk] : 0.f;
            *(float2*)&sAd[0][kk][2 * r] = make_float2(v, v);
        }
        for (int idx = tid; idx < 8 * NC; idx += 256) {
            int kk = idx / NC, o = idx - kk * NC;
            sB[0][kk][o] = g_B[kk * NC + o];
        }
    }
    __syncthreads();

    for (int c = 0; c < nchunk; c++) {
        int cur = c & 1, nxt = cur ^ 1;
        if (c + 1 < nchunk) {
            int k0 = (c + 1) * 8;
#pragma unroll
            for (int p = 0; p < 4; p++) {
                int idx = tid + p * 256;
                int kk = idx & 7, r = idx >> 3;
                int k = k0 + kk;
                float v = (k < KD) ? A[(rowBase + r) * lda + k] : 0.f;
                *(float2*)&sAd[nxt][kk][2 * r] = make_float2(v, v);
            }
            for (int idx = tid; idx < 8 * NC; idx += 256) {
                int kk = idx / NC, o = idx - kk * NC;
                sB[nxt][kk][o] = g_B[(k0 + kk) * NC + o];
            }
        }
#pragma unroll
        for (int kk = 0; kk < 8; kk++) {
            unsigned long long av[4];
#pragma unroll
            for (int m = 0; m < 4; m++)
                av[m] = *(const unsigned long long*)&sAd[cur][kk][(ty * 4 + m) * 2];
#pragma unroll
            for (int n = 0; n < 9; n++) {
                unsigned long long bd =
                    *(const unsigned long long*)&sB[cur][kk][tx * 18 + 2 * n];
#pragma unroll
                for (int m = 0; m < 4; m++)
                    asm("fma.rn.f32x2 %0, %1, %2, %0;"
                        : "+l"(acc[n][m]) : "l"(av[m]), "l"(bd));
            }
        }
        __syncthreads();
    }

    // epilogue: acc[n][m] = C[row ty*4+m][cols tx*18+2n, +2n+1]
#pragma unroll
    for (int n = 0; n < 9; n++) {
        int col = tx * 18 + 2 * n;
#pragma unroll
        for (int m = 0; m < 4; m++) {
            float lo, hi;
            asm("mov.b64 {%0,%1},%2;" : "=f"(lo), "=f"(hi) : "l"(acc[n][m]));
            *(float2*)&g_qkv[(rowBase + ty * 4 + m) * NC + col] = make_float2(lo, hi);
        }
    }
}

// ---------------- fused attention + LN + sigmoid-linear ----------------
// Lane map: warp w owns group g=w; lanes are 32 consecutive tokens.
// k/v stride 49 (odd) -> conflict-free; rel_t broadcast; qx stride 52 (16B align).
struct AttSmem {
    float k[TT + 2 * HALF][49];
    float v[TT + 2 * HALF][49];
    float qx[TT][52];
    float rel[KW][MC];            // transposed: rel[j][c], broadcast reads
    float w[OUTF][MC];
    float gamma[MC];
    float beta[MC];
    float bias[OUTF];
};

template <bool FIRST>
__global__ __launch_bounds__(256)
void att_kernel(const float* __restrict__ rel,
                const float* __restrict__ lng, const float* __restrict__ lnb,
                const float* __restrict__ Wlin, const float* __restrict__ blin,
                float* __restrict__ out_lin,    // sigmoid(linear) [NROW,88]
                float* __restrict__ out_a)      // attn weights [NROW,8,31] (stage1 only)
{
    extern __shared__ char smraw[];
    AttSmem& sm = *reinterpret_cast<AttSmem*>(smraw);
    int tid = threadIdx.x;
    int lane = tid & 31;
    int wrp  = tid >> 5;          // warp id = attention group
    int t0 = blockIdx.x * TT;
    int b  = blockIdx.y;

    // ---- stage K/V window, Q tile, rel (transposed), weights ----
    for (int idx = tid; idx < (TT + 2 * HALF) * MC; idx += 256) {
        int r = idx / MC, c = idx - r * MC;
        int t = t0 - HALF + r;
        float kv = 0.f, vv = 0.f;
        if (t >= 0 && t < S) {
            int g = (b * S + t) * NC;
            kv = g_qkv[g + MC + c];
            vv = g_qkv[g + 2 * MC + c];
        }
        sm.k[r][c] = kv;
        sm.v[r][c] = vv;
    }
    for (int idx = tid; idx < TT * MC; idx += 256) {
        int r = idx / MC, c = idx - r * MC;
        sm.qx[r][c] = g_qkv[(b * S + t0 + r) * NC + c];
    }
    for (int idx = tid; idx < KW * MC; idx += 256) {
        int j = idx / MC, c = idx - j * MC;
        sm.rel[j][c] = rel[c * KW + j];           // transpose on stage
    }
    for (int idx = tid; idx < OUTF * MC; idx += 256)
        sm.w[idx / MC][idx % MC] = Wlin[idx];
    if (tid < MC) { sm.gamma[tid] = lng[tid]; sm.beta[tid] = lnb[tid]; }
    if (tid < OUTF) sm.bias[tid] = blin[tid];
    __syncthreads();

    // ---- windowed attention: warp wrp handles group wrp, lanes = tokens ----
    int c0 = wrp * 6;
#pragma unroll
    for (int i = 0; i < TT / 32; i++) {
        int tl = i * 32 + lane;
        float qv[6];
#pragma unroll
        for (int c = 0; c < 6; c++) qv[c] = sm.qx[tl][c0 + c];

        float e[KW];
        float mx = -1e30f;
#pragma unroll
        for (int j = 0; j < KW; j++) {
            float s = 0.f;
#pragma unroll
            for (int c = 0; c < 6; c++)
                s = fmaf(qv[c], sm.k[tl + j][c0 + c] + sm.rel[j][c0 + c], s);
            e[j] = s;
            mx = fmaxf(mx, s);
        }
        float sum = 0.f;
#pragma unroll
        for (int j = 0; j < KW; j++) { e[j] = __expf(e[j] - mx); sum += e[j]; }
        float inv = 1.f / sum;

        if (FIRST) {
            int ab = ((b * S + t0 + tl) * 8 + wrp) * KW;
#pragma unroll
            for (int j = 0; j < KW; j++) out_a[ab + j] = e[j] * inv;
        }

        float xo[6];
#pragma unroll
        for (int c = 0; c < 6; c++) {
            float s = 0.f;
#pragma unroll
            for (int j = 0; j < KW; j++) s = fmaf(e[j], sm.v[tl + j][c0 + c], s);
            xo[c] = s * inv;
        }
#pragma unroll
        for (int c = 0; c < 6; c++) sm.qx[tl][c0 + c] = xo[c];
    }
    __syncthreads();

    // ---- LayerNorm over 48 channels ----
    if (tid < TT) {
        float s = 0.f;
        for (int c = 0; c < MC; c++) s += sm.qx[tid][c];
        float mu = s * (1.f / MC);
        float v2 = 0.f;
        for (int c = 0; c < MC; c++) { float d = sm.qx[tid][c] - mu; v2 = fmaf(d, d, v2); }
        float rstd = rsqrtf(v2 * (1.f / MC) + 1e-5f);
        int grow = b * S + t0 + tid;
        for (int c = 0; c < MC; c++) {
            float xn = (sm.qx[tid][c] - mu) * rstd * sm.gamma[c] + sm.beta[c];
            sm.qx[tid][c] = xn;
            if (FIRST) g_y[grow * IN2 + OUTF + c] = xn;
        }
    }
    __syncthreads();

    // ---- sigmoid(x_ln @ W^T + b): TT x 88 outputs ----
    for (int i = 0; i < (TT * OUTF) / 256; i++) {
        int item = i * 256 + tid;
        int tl = item / OUTF, o = item - tl * OUTF;
        const float4* xr = (const float4*)sm.qx[tl];
        const float4* wr = (const float4*)sm.w[o];
        float acc = sm.bias[o];
#pragma unroll
        for (int c = 0; c < MC / 4; c++) {
            float4 xv = xr[c], wv = wr[c];
            acc = fmaf(xv.x, wv.x, acc); acc = fmaf(xv.y, wv.y, acc);
            acc = fmaf(xv.z, wv.z, acc); acc = fmaf(xv.w, wv.w, acc);
        }
        float sg = 1.f / (1.f + __expf(-acc));
        int grow = b * S + t0 + tl;
        out_lin[grow * OUTF + o] = sg;
        if (FIRST) g_y[grow * IN2 + o] = sg;   // concat head
    }
}

// ---------------- launch ----------------
extern "C" void kernel_launch(void* const* d_in, const int* in_sizes, int n_in,
                              void* d_out, int out_size) {
    (void)in_sizes; (void)n_in; (void)out_size;
    const float* spec = (const float*)d_in[0];
    const float* Wq1  = (const float*)d_in[1];
    const float* Wk1  = (const float*)d_in[2];
    const float* Wv1  = (const float*)d_in[3];
    const float* rel1 = (const float*)d_in[4];
    const float* ln1g = (const float*)d_in[5];
    const float* ln1b = (const float*)d_in[6];
    const float* Wo   = (const float*)d_in[7];
    const float* bo   = (const float*)d_in[8];
    const float* Wq2  = (const float*)d_in[9];
    const float* Wk2  = (const float*)d_in[10];
    const float* Wv2  = (const float*)d_in[11];
    const float* rel2 = (const float*)d_in[12];
    const float* ln2g = (const float*)d_in[13];
    const float* ln2b = (const float*)d_in[14];
    const float* Wf   = (const float*)d_in[15];
    const float* bf   = (const float*)d_in[16];

    float* out = (float*)d_out;
    float* out_frame = out;                        // [NROW, 88]
    float* out_onset = out + (size_t)NROW * OUTF;  // [NROW, 88]
    float* out_a     = out + (size_t)2 * NROW * OUTF;  // [NROW, 8, 31]

    cudaFuncSetAttribute(att_kernel<true>,  cudaFuncAttributeMaxDynamicSharedMemorySize,
                         (int)sizeof(AttSmem));
    cudaFuncSetAttribute(att_kernel<false>, cudaFuncAttributeMaxDynamicSharedMemorySize,
                         (int)sizeof(AttSmem));

    dim3 attGrid(S / TT, BATCH);

    // stage 1
    prep_B<<<(232 * NC + 255) / 256, 256>>>(Wq1, Wk1, Wv1, IN1, 232);
    gemm_k<false><<<NROW / BM, 256>>>(spec, IN1, IN1, 232);
    att_kernel<true><<<attGrid, 256, sizeof(AttSmem)>>>(
        rel1, ln1g, ln1b, Wo, bo, out_onset, out_a);

    // stage 2
    prep_B<<<(IN2 * NC + 255) / 256, 256>>>(Wq2, Wk2, Wv2, IN2, IN2);
    gemm_k<true><<<NROW / BM, 256>>>(nullptr, IN2, IN2, IN2);
    att_kernel<false><<<attGrid, 256, sizeof(AttSmem)>>>(
        rel2, ln2g, ln2b, Wf, bf, out_frame, nullptr);
}